// round 10
// baseline (speedup 1.0000x reference)
#include <cuda_runtime.h>
#include <cstdint>

// YOLO detection decode: x (64, 255, 52, 52) f32 -> out (64, 8112, 85) f32
// v10 = v9 + 2-tile-per-block software pipeline with double-buffered smem.
//   Tile pair lives in one (batch,anchor) plane. LDGs for tile1 are issued
//   BEFORE tile0's STG phase, hiding DRAM read latency behind the store loop
//   and keeping reads in flight across the whole block (de-bursts DRAM).
//   launch_bounds(256,6): 42 regs so the 5-float4 prefetch stays in registers.

#define G 52
#define GG 2704              // G*G
#define GGV 676              // GG/4 (channel stride in float4)
#define IN_PER_B 689520      // 255*GG
#define NE 85
#define TILE 52
#define QV 13                // TILE/4
#define NV (NE * QV)         // 1105 float4 per tile
#define THREADS 256

__constant__ float c_aw[3] = {10.0f, 16.0f, 33.0f};
__constant__ float c_ah[3] = {13.0f, 30.0f, 23.0f};

__device__ __forceinline__ float fsigmoid(float v) {
    // sigmoid(v) = 0.5 + 0.5*tanh(0.5*v); MUFU.TANH, abs err ~2^-12
    float t;
    asm("tanh.approx.f32 %0, %1;" : "=f"(t) : "f"(0.5f * v));
    return fmaf(0.5f, t, 0.5f);
}

__device__ __forceinline__ void load5(const float4* __restrict__ src,
                                      float4 r[5], int tid) {
    #define SRCIDX(j) ((j) / QV * GGV + ((j) - (j) / QV * QV))
    r[0] = src[SRCIDX(tid)];
    r[1] = src[SRCIDX(tid + THREADS)];
    r[2] = src[SRCIDX(tid + 2 * THREADS)];
    r[3] = src[SRCIDX(tid + 3 * THREADS)];
    if (tid + 4 * THREADS < NV) r[4] = src[SRCIDX(tid + 4 * THREADS)];
    #undef SRCIDX
}

__device__ __forceinline__ void transform_store(
    float* __restrict__ s, float4 v, int j, int p0, float aw, float ah) {
    const int e = j / QV;
    const int q = j - e * QV;
    const int lp = q * 4;

    float o0, o1, o2, o3;
    if (e >= 4) {
        o0 = fsigmoid(v.x); o1 = fsigmoid(v.y);
        o2 = fsigmoid(v.z); o3 = fsigmoid(v.w);
    } else if (e == 0) {
        const int p = p0 + lp;
        o0 = (fsigmoid(v.x) + (float)((p    ) % G)) * 8.0f;
        o1 = (fsigmoid(v.y) + (float)((p + 1) % G)) * 8.0f;
        o2 = (fsigmoid(v.z) + (float)((p + 2) % G)) * 8.0f;
        o3 = (fsigmoid(v.w) + (float)((p + 3) % G)) * 8.0f;
    } else if (e == 1) {
        const int p = p0 + lp;
        o0 = (fsigmoid(v.x) + (float)((p    ) / G)) * 8.0f;
        o1 = (fsigmoid(v.y) + (float)((p + 1) / G)) * 8.0f;
        o2 = (fsigmoid(v.z) + (float)((p + 2) / G)) * 8.0f;
        o3 = (fsigmoid(v.w) + (float)((p + 3) / G)) * 8.0f;
    } else if (e == 2) {
        o0 = __expf(v.x) * aw; o1 = __expf(v.y) * aw;
        o2 = __expf(v.z) * aw; o3 = __expf(v.w) * aw;
    } else { // e == 3
        o0 = __expf(v.x) * ah; o1 = __expf(v.y) * ah;
        o2 = __expf(v.z) * ah; o3 = __expf(v.w) * ah;
    }
    float* sp = s + lp * NE + e;     // output layout: word = lp*85 + e
    sp[0 * NE] = o0; sp[1 * NE] = o1; sp[2 * NE] = o2; sp[3 * NE] = o3;
}

__device__ __forceinline__ void ts5(float* __restrict__ s, const float4 r[5],
                                    int tid, int p0, float aw, float ah) {
    transform_store(s, r[0], tid,               p0, aw, ah);
    transform_store(s, r[1], tid + THREADS,     p0, aw, ah);
    transform_store(s, r[2], tid + 2 * THREADS, p0, aw, ah);
    transform_store(s, r[3], tid + 3 * THREADS, p0, aw, ah);
    if (tid + 4 * THREADS < NV)
        transform_store(s, r[4], tid + 4 * THREADS, p0, aw, ah);
}

__device__ __forceinline__ void stg5(float* __restrict__ dst,
                                     const float* __restrict__ s, int tid) {
    float4* __restrict__ d = reinterpret_cast<float4*>(dst);
    const float4* __restrict__ ss = reinterpret_cast<const float4*>(s);
    __stcs(d + tid,               ss[tid]);
    __stcs(d + tid + THREADS,     ss[tid + THREADS]);
    __stcs(d + tid + 2 * THREADS, ss[tid + 2 * THREADS]);
    __stcs(d + tid + 3 * THREADS, ss[tid + 3 * THREADS]);
    if (tid + 4 * THREADS < NV)
        __stcs(d + tid + 4 * THREADS, ss[tid + 4 * THREADS]);
}

__global__ __launch_bounds__(THREADS, 6)
void det_decode_kernel(const float* __restrict__ x, float* __restrict__ out) {
    __shared__ alignas(128) float sA[TILE * NE];   // 17,680 B
    __shared__ alignas(128) float sB[TILE * NE];   // 17,680 B

    // Block -> pair of adjacent tiles in one (b, a) plane.
    // planes = 192, pairs/plane = 26, blocks = 4992.
    const int c    = blockIdx.x;
    const int P    = c / 26;          // plane index 0..191
    const int pair = c - P * 26;
    const int b    = P / 3;
    const int a    = P - b * 3;
    const int p0   = pair * 104;      // tile0 spatial offset; tile1 = p0+52

    const float4* __restrict__ src0 = reinterpret_cast<const float4*>(
        x + (size_t)b * IN_PER_B + (size_t)(a * NE) * GG + p0);
    const float4* __restrict__ src1 = src0 + 13;

    const float aw = c_aw[a];
    const float ah = c_ah[a];
    const int tid = threadIdx.x;
    float* dst0 = out + (size_t)c * (2 * TILE * NE);   // 8840 floats per block

    float4 r[5];

    // Tile 0: load -> transform -> stage
    load5(src0, r, tid);
    ts5(sA, r, tid, p0, aw, ah);
    __syncthreads();

    // Tile 1 loads issued BEFORE tile 0's store phase (latency hidden).
    load5(src1, r, tid);

    // Tile 0: store out of sA
    stg5(dst0, sA, tid);

    // Tile 1: transform -> stage into sB (no sync needed: different buffer)
    ts5(sB, r, tid, p0 + TILE, aw, ah);
    __syncthreads();

    // Tile 1: store out of sB
    stg5(dst0 + TILE * NE, sB, tid);
}

extern "C" void kernel_launch(void* const* d_in, const int* in_sizes, int n_in,
                              void* d_out, int out_size) {
    const float* x = (const float*)d_in[0];
    float* out = (float*)d_out;
    const int blocks = out_size / (2 * TILE * NE);   // 4992
    det_decode_kernel<<<blocks, THREADS>>>(x, out);
}

// round 11
// speedup vs baseline: 1.4765x; 1.4765x over previous
#include <cuda_runtime.h>
#include <cstdint>

// YOLO detection decode: x (64, 255, 52, 52) f32 -> out (64, 8112, 85) f32
// v11 = v9 body (unchanged, best: 56.1us) inside a PERSISTENT grid-stride loop.
//   1216 blocks (152 SMs x 8) each iterate over tiles:
//     load5 -> transform/STS -> sync -> LDS/STG -> sync -> next tile
//   Next tile's batched LDGs issue while previous STGs drain (bar.sync only
//   drains STS, not global writes) -> reads in flight across store phases,
//   blocks desync after iter 1 -> smooth DRAM demand, no wave quantization.

#define G 52
#define GG 2704              // G*G
#define GGV 676              // GG/4 (channel stride in float4)
#define IN_PER_B 689520      // 255*GG
#define NE 85
#define TILE 52
#define QV 13                // TILE/4
#define NV (NE * QV)         // 1105 float4 per tile
#define TILES_PER_PLANE 52
#define NTILES 9984
#define THREADS 256
#define GRID 1216            // 152 SMs * 8 blocks

__constant__ float c_aw[3] = {10.0f, 16.0f, 33.0f};
__constant__ float c_ah[3] = {13.0f, 30.0f, 23.0f};

__device__ __forceinline__ float fsigmoid(float v) {
    // sigmoid(v) = 0.5 + 0.5*tanh(0.5*v); MUFU.TANH, abs err ~2^-12
    float t;
    asm("tanh.approx.f32 %0, %1;" : "=f"(t) : "f"(0.5f * v));
    return fmaf(0.5f, t, 0.5f);
}

__device__ __forceinline__ void transform_store(
    float* __restrict__ s, float4 v, int j, int p0, float aw, float ah) {
    const int e = j / QV;
    const int q = j - e * QV;
    const int lp = q * 4;

    float o0, o1, o2, o3;
    if (e >= 4) {
        o0 = fsigmoid(v.x); o1 = fsigmoid(v.y);
        o2 = fsigmoid(v.z); o3 = fsigmoid(v.w);
    } else if (e == 0) {
        const int p = p0 + lp;
        o0 = (fsigmoid(v.x) + (float)((p    ) % G)) * 8.0f;
        o1 = (fsigmoid(v.y) + (float)((p + 1) % G)) * 8.0f;
        o2 = (fsigmoid(v.z) + (float)((p + 2) % G)) * 8.0f;
        o3 = (fsigmoid(v.w) + (float)((p + 3) % G)) * 8.0f;
    } else if (e == 1) {
        const int p = p0 + lp;
        o0 = (fsigmoid(v.x) + (float)((p    ) / G)) * 8.0f;
        o1 = (fsigmoid(v.y) + (float)((p + 1) / G)) * 8.0f;
        o2 = (fsigmoid(v.z) + (float)((p + 2) / G)) * 8.0f;
        o3 = (fsigmoid(v.w) + (float)((p + 3) / G)) * 8.0f;
    } else if (e == 2) {
        o0 = __expf(v.x) * aw; o1 = __expf(v.y) * aw;
        o2 = __expf(v.z) * aw; o3 = __expf(v.w) * aw;
    } else { // e == 3
        o0 = __expf(v.x) * ah; o1 = __expf(v.y) * ah;
        o2 = __expf(v.z) * ah; o3 = __expf(v.w) * ah;
    }
    float* sp = s + lp * NE + e;     // output layout: word = lp*85 + e
    sp[0 * NE] = o0; sp[1 * NE] = o1; sp[2 * NE] = o2; sp[3 * NE] = o3;
}

__global__ __launch_bounds__(THREADS, 8)
void det_decode_kernel(const float* __restrict__ x, float* __restrict__ out) {
    __shared__ alignas(128) float s[TILE * NE];   // 17,680 B

    const int tid = threadIdx.x;
    const int j0 = tid;
    const int j1 = tid + THREADS;
    const int j2 = tid + 2 * THREADS;
    const int j3 = tid + 3 * THREADS;
    const int j4 = tid + 4 * THREADS;          // valid only for tid < 81
    const bool tail = (j4 < NV);

    for (int t = blockIdx.x; t < NTILES; t += GRID) {
        // Tile -> (b, a, p0). tiles/anchor = 52, tiles/batch = 156.
        const int b   = t / 156;
        const int rem = t - b * 156;
        const int a   = rem / TILES_PER_PLANE;
        const int pt  = rem - a * TILES_PER_PLANE;
        const int p0  = pt * TILE;

        const float4* __restrict__ src = reinterpret_cast<const float4*>(
            x + (size_t)b * IN_PER_B + (size_t)(a * NE) * GG + p0);

        const float aw = c_aw[a];
        const float ah = c_ah[a];

        // Batched loads (MLP = 5 per thread), issued right after sync2 of the
        // previous iteration while its STGs are still draining.
        #define SRCIDX(j) ((j) / QV * GGV + ((j) - (j) / QV * QV))
        const float4 v0 = src[SRCIDX(j0)];
        const float4 v1 = src[SRCIDX(j1)];
        const float4 v2 = src[SRCIDX(j2)];
        const float4 v3 = src[SRCIDX(j3)];
        float4 v4 = make_float4(0.f, 0.f, 0.f, 0.f);
        if (tail) v4 = src[SRCIDX(j4)];
        #undef SRCIDX

        transform_store(s, v0, j0, p0, aw, ah);
        transform_store(s, v1, j1, p0, aw, ah);
        transform_store(s, v2, j2, p0, aw, ah);
        transform_store(s, v3, j3, p0, aw, ah);
        if (tail) transform_store(s, v4, j4, p0, aw, ah);

        __syncthreads();

        // Store phase: contiguous span of TILE*NE = 4420 floats.
        float4* __restrict__ dst =
            reinterpret_cast<float4*>(out + (size_t)t * (TILE * NE));
        const float4* __restrict__ ss = reinterpret_cast<const float4*>(s);
        __stcs(dst + j0, ss[j0]);
        __stcs(dst + j1, ss[j1]);
        __stcs(dst + j2, ss[j2]);
        __stcs(dst + j3, ss[j3]);
        if (tail) __stcs(dst + j4, ss[j4]);

        // Protect smem from next iteration's STS until all warps read it.
        __syncthreads();
    }
}

extern "C" void kernel_launch(void* const* d_in, const int* in_sizes, int n_in,
                              void* d_out, int out_size) {
    const float* x = (const float*)d_in[0];
    float* out = (float*)d_out;
    det_decode_kernel<<<GRID, THREADS>>>(x, out);
}

// round 12
// speedup vs baseline: 1.5285x; 1.0352x over previous
#include <cuda_runtime.h>
#include <cstdint>

// YOLO detection decode: x (64, 255, 52, 52) f32 -> out (64, 8112, 85) f32
// v12 = v9 body, 2 adjacent tiles per block through ONE smem buffer:
//   load5(t0) -> ts -> sync -> stg -> sync -> load5(t1) -> ts -> sync -> stg
//   t1's batched LDGs issue while t0's STGs drain (overlap), residency stays
//   8 CTA/SM (no double buffer, no held prefetch regs), 4992 blocks = 4.1
//   waves -> work-stealing desync (avoids v11's one-wave phase lock).

#define G 52
#define GG 2704              // G*G
#define GGV 676              // GG/4 (channel stride in float4)
#define IN_PER_B 689520      // 255*GG
#define NE 85
#define TILE 52
#define QV 13                // TILE/4
#define NV (NE * QV)         // 1105 float4 per tile
#define TILES_PER_PLANE 52
#define THREADS 256

__constant__ float c_aw[3] = {10.0f, 16.0f, 33.0f};
__constant__ float c_ah[3] = {13.0f, 30.0f, 23.0f};

__device__ __forceinline__ float fsigmoid(float v) {
    // sigmoid(v) = 0.5 + 0.5*tanh(0.5*v); MUFU.TANH, abs err ~2^-12
    float t;
    asm("tanh.approx.f32 %0, %1;" : "=f"(t) : "f"(0.5f * v));
    return fmaf(0.5f, t, 0.5f);
}

__device__ __forceinline__ void transform_store(
    float* __restrict__ s, float4 v, int j, int p0, float aw, float ah) {
    const int e = j / QV;
    const int q = j - e * QV;
    const int lp = q * 4;

    float o0, o1, o2, o3;
    if (e >= 4) {
        o0 = fsigmoid(v.x); o1 = fsigmoid(v.y);
        o2 = fsigmoid(v.z); o3 = fsigmoid(v.w);
    } else if (e == 0) {
        const int p = p0 + lp;
        o0 = (fsigmoid(v.x) + (float)((p    ) % G)) * 8.0f;
        o1 = (fsigmoid(v.y) + (float)((p + 1) % G)) * 8.0f;
        o2 = (fsigmoid(v.z) + (float)((p + 2) % G)) * 8.0f;
        o3 = (fsigmoid(v.w) + (float)((p + 3) % G)) * 8.0f;
    } else if (e == 1) {
        const int p = p0 + lp;
        o0 = (fsigmoid(v.x) + (float)((p    ) / G)) * 8.0f;
        o1 = (fsigmoid(v.y) + (float)((p + 1) / G)) * 8.0f;
        o2 = (fsigmoid(v.z) + (float)((p + 2) / G)) * 8.0f;
        o3 = (fsigmoid(v.w) + (float)((p + 3) / G)) * 8.0f;
    } else if (e == 2) {
        o0 = __expf(v.x) * aw; o1 = __expf(v.y) * aw;
        o2 = __expf(v.z) * aw; o3 = __expf(v.w) * aw;
    } else { // e == 3
        o0 = __expf(v.x) * ah; o1 = __expf(v.y) * ah;
        o2 = __expf(v.z) * ah; o3 = __expf(v.w) * ah;
    }
    float* sp = s + lp * NE + e;     // output layout: word = lp*85 + e
    sp[0 * NE] = o0; sp[1 * NE] = o1; sp[2 * NE] = o2; sp[3 * NE] = o3;
}

__device__ __forceinline__ void do_tile(
    float* __restrict__ s, const float* __restrict__ x,
    float* __restrict__ out, int t, int tid) {
    // Tile -> (b, a, p0). tiles/anchor = 52, tiles/batch = 156.
    const int b   = t / 156;
    const int rem = t - b * 156;
    const int a   = rem / TILES_PER_PLANE;
    const int pt  = rem - a * TILES_PER_PLANE;
    const int p0  = pt * TILE;

    const float4* __restrict__ src = reinterpret_cast<const float4*>(
        x + (size_t)b * IN_PER_B + (size_t)(a * NE) * GG + p0);

    const float aw = c_aw[a];
    const float ah = c_ah[a];

    const int j0 = tid;
    const int j1 = tid + THREADS;
    const int j2 = tid + 2 * THREADS;
    const int j3 = tid + 3 * THREADS;
    const int j4 = tid + 4 * THREADS;          // valid only for tid < 81
    const bool tail = (j4 < NV);

    // Batched loads (MLP = 5/thread), back-to-back before any transform.
    #define SRCIDX(j) ((j) / QV * GGV + ((j) - (j) / QV * QV))
    const float4 v0 = src[SRCIDX(j0)];
    const float4 v1 = src[SRCIDX(j1)];
    const float4 v2 = src[SRCIDX(j2)];
    const float4 v3 = src[SRCIDX(j3)];
    float4 v4 = make_float4(0.f, 0.f, 0.f, 0.f);
    if (tail) v4 = src[SRCIDX(j4)];
    #undef SRCIDX

    transform_store(s, v0, j0, p0, aw, ah);
    transform_store(s, v1, j1, p0, aw, ah);
    transform_store(s, v2, j2, p0, aw, ah);
    transform_store(s, v3, j3, p0, aw, ah);
    if (tail) transform_store(s, v4, j4, p0, aw, ah);

    __syncthreads();

    // Store phase: contiguous span of TILE*NE = 4420 floats.
    float4* __restrict__ dst =
        reinterpret_cast<float4*>(out + (size_t)t * (TILE * NE));
    const float4* __restrict__ ss = reinterpret_cast<const float4*>(s);
    __stcs(dst + j0, ss[j0]);
    __stcs(dst + j1, ss[j1]);
    __stcs(dst + j2, ss[j2]);
    __stcs(dst + j3, ss[j3]);
    if (tail) __stcs(dst + j4, ss[j4]);
}

__global__ __launch_bounds__(THREADS, 8)
void det_decode_kernel(const float* __restrict__ x, float* __restrict__ out) {
    __shared__ alignas(128) float s[TILE * NE];   // 17,680 B

    const int tid = threadIdx.x;
    const int t0 = 2 * blockIdx.x;

    do_tile(s, x, out, t0, tid);
    __syncthreads();                  // smem safe to overwrite
    do_tile(s, x, out, t0 + 1, tid);  // t1 LDGs overlap t0 STG drain
}

extern "C" void kernel_launch(void* const* d_in, const int* in_sizes, int n_in,
                              void* d_out, int out_size) {
    const float* x = (const float*)d_in[0];
    float* out = (float*)d_out;
    const int blocks = out_size / (2 * TILE * NE);   // 4992
    det_decode_kernel<<<blocks, THREADS>>>(x, out);
}

// round 14
// speedup vs baseline: 1.5364x; 1.0052x over previous
#include <cuda_runtime.h>
#include <cstdint>

// YOLO detection decode: x (64, 255, 52, 52) f32 -> out (64, 8112, 85) f32
// v13 = v9 scaled 2x: TILE=104, THREADS=512, launch_bounds(512,4).
//   Per-thread body identical to v9 (batched 4+1 LDG.128, tanh-sigmoid
//   transform, scalar-STS transpose, contiguous float4 STG). Same 64 warps/SM;
//   half the CTA launches, barriers and tile-boundary L2 sharing.

#define G 52
#define GG 2704              // G*G
#define GGV 676              // GG/4 (channel stride in float4)
#define IN_PER_B 689520      // 255*GG
#define NE 85
#define TILE 104
#define QV 26                // TILE/4
#define NV (NE * QV)         // 2210 float4 per tile
#define TILES_PER_PLANE 26   // GG / TILE
#define THREADS 512

__constant__ float c_aw[3] = {10.0f, 16.0f, 33.0f};
__constant__ float c_ah[3] = {13.0f, 30.0f, 23.0f};

__device__ __forceinline__ float fsigmoid(float v) {
    // sigmoid(v) = 0.5 + 0.5*tanh(0.5*v); MUFU.TANH, abs err ~2^-12
    float t;
    asm("tanh.approx.f32 %0, %1;" : "=f"(t) : "f"(0.5f * v));
    return fmaf(0.5f, t, 0.5f);
}

__device__ __forceinline__ void transform_store(
    float* __restrict__ s, float4 v, int j, int p0, float aw, float ah) {
    const int e = j / QV;
    const int q = j - e * QV;
    const int lp = q * 4;

    float o0, o1, o2, o3;
    if (e >= 4) {
        o0 = fsigmoid(v.x); o1 = fsigmoid(v.y);
        o2 = fsigmoid(v.z); o3 = fsigmoid(v.w);
    } else if (e == 0) {
        const int p = p0 + lp;
        o0 = (fsigmoid(v.x) + (float)((p    ) % G)) * 8.0f;
        o1 = (fsigmoid(v.y) + (float)((p + 1) % G)) * 8.0f;
        o2 = (fsigmoid(v.z) + (float)((p + 2) % G)) * 8.0f;
        o3 = (fsigmoid(v.w) + (float)((p + 3) % G)) * 8.0f;
    } else if (e == 1) {
        const int p = p0 + lp;
        o0 = (fsigmoid(v.x) + (float)((p    ) / G)) * 8.0f;
        o1 = (fsigmoid(v.y) + (float)((p + 1) / G)) * 8.0f;
        o2 = (fsigmoid(v.z) + (float)((p + 2) / G)) * 8.0f;
        o3 = (fsigmoid(v.w) + (float)((p + 3) / G)) * 8.0f;
    } else if (e == 2) {
        o0 = __expf(v.x) * aw; o1 = __expf(v.y) * aw;
        o2 = __expf(v.z) * aw; o3 = __expf(v.w) * aw;
    } else { // e == 3
        o0 = __expf(v.x) * ah; o1 = __expf(v.y) * ah;
        o2 = __expf(v.z) * ah; o3 = __expf(v.w) * ah;
    }
    float* sp = s + lp * NE + e;     // output layout: word = lp*85 + e
    sp[0 * NE] = o0; sp[1 * NE] = o1; sp[2 * NE] = o2; sp[3 * NE] = o3;
}

__global__ __launch_bounds__(THREADS, 4)
void det_decode_kernel(const float* __restrict__ x, float* __restrict__ out) {
    __shared__ alignas(128) float s[TILE * NE];   // 35,360 B

    // Tile -> (b, a, p0). tiles/anchor = 26, tiles/batch = 78.
    const int t   = blockIdx.x;
    const int b   = t / 78;
    const int rem = t - b * 78;
    const int a   = rem / TILES_PER_PLANE;
    const int pt  = rem - a * TILES_PER_PLANE;
    const int p0  = pt * TILE;

    const float4* __restrict__ src = reinterpret_cast<const float4*>(
        x + (size_t)b * IN_PER_B + (size_t)(a * NE) * GG + p0);

    const float aw = c_aw[a];
    const float ah = c_ah[a];

    const int tid = threadIdx.x;
    const int j0 = tid;
    const int j1 = tid + THREADS;
    const int j2 = tid + 2 * THREADS;
    const int j3 = tid + 3 * THREADS;
    const int j4 = tid + 4 * THREADS;          // valid only for tid < 162
    const bool tail = (j4 < NV);

    // Batched loads (MLP = 5 per thread), back-to-back before any transform.
    #define SRCIDX(j) ((j) / QV * GGV + ((j) - (j) / QV * QV))
    const float4 v0 = src[SRCIDX(j0)];
    const float4 v1 = src[SRCIDX(j1)];
    const float4 v2 = src[SRCIDX(j2)];
    const float4 v3 = src[SRCIDX(j3)];
    float4 v4 = make_float4(0.f, 0.f, 0.f, 0.f);
    if (tail) v4 = src[SRCIDX(j4)];
    #undef SRCIDX

    transform_store(s, v0, j0, p0, aw, ah);
    transform_store(s, v1, j1, p0, aw, ah);
    transform_store(s, v2, j2, p0, aw, ah);
    transform_store(s, v3, j3, p0, aw, ah);
    if (tail) transform_store(s, v4, j4, p0, aw, ah);

    __syncthreads();

    // Store phase: contiguous span of TILE*NE = 8840 floats.
    float4* __restrict__ dst =
        reinterpret_cast<float4*>(out + (size_t)t * (TILE * NE));
    const float4* __restrict__ ss = reinterpret_cast<const float4*>(s);
    __stcs(dst + j0, ss[j0]);
    __stcs(dst + j1, ss[j1]);
    __stcs(dst + j2, ss[j2]);
    __stcs(dst + j3, ss[j3]);
    if (tail) __stcs(dst + j4, ss[j4]);
}

extern "C" void kernel_launch(void* const* d_in, const int* in_sizes, int n_in,
                              void* d_out, int out_size) {
    const float* x = (const float*)d_in[0];
    float* out = (float*)d_out;
    const int blocks = out_size / (TILE * NE);   // 4992
    det_decode_kernel<<<blocks, THREADS>>>(x, out);
}

// round 15
// speedup vs baseline: 1.6433x; 1.0696x over previous
#include <cuda_runtime.h>
#include <cstdint>

// YOLO detection decode: x (64, 255, 52, 52) f32 -> out (64, 8112, 85) f32
// FINAL = v9 (best: 56.1us, DRAM 72%). Convergence established over R10-R14:
//   every structural deviation (double-buffer pipeline, persistent grid,
//   2-tile chunks, 2x scale-up) regressed 5-38us. Optimal configuration:
//   - 9984 small independent blocks (256 thr, one 52-row tile in one
//     (batch,anchor) plane) -> natural phase desync across 8 CTAs/SM
//   - batched 4+1 LDG.128 per thread issued back-to-back (MLP=5)
//   - default-cached loads (boundary 32B sectors shared between tiles;
//     evict-first caused ~8% DRAM re-reads)
//   - tanh.approx sigmoid (1 MUFU), exp only for w/h channels
//   - scalar-STS transpose into output-layout smem (~2-way conflicts;
//     swizzles cost more ALU than they save)
//   - contiguous float4 streaming STG of the tile's 17680B output span

#define G 52
#define GG 2704              // G*G
#define GGV 676              // GG/4 (channel stride in float4)
#define IN_PER_B 689520      // 255*GG
#define NE 85
#define TILE 52
#define QV 13                // TILE/4
#define NV (NE * QV)         // 1105 float4 per tile
#define TILES_PER_PLANE 52
#define THREADS 256

__constant__ float c_aw[3] = {10.0f, 16.0f, 33.0f};
__constant__ float c_ah[3] = {13.0f, 30.0f, 23.0f};

__device__ __forceinline__ float fsigmoid(float v) {
    // sigmoid(v) = 0.5 + 0.5*tanh(0.5*v); MUFU.TANH, abs err ~2^-12
    float t;
    asm("tanh.approx.f32 %0, %1;" : "=f"(t) : "f"(0.5f * v));
    return fmaf(0.5f, t, 0.5f);
}

__device__ __forceinline__ void transform_store(
    float* __restrict__ s, float4 v, int j, int p0, float aw, float ah) {
    const int e = j / QV;
    const int q = j - e * QV;
    const int lp = q * 4;

    float o0, o1, o2, o3;
    if (e >= 4) {
        o0 = fsigmoid(v.x); o1 = fsigmoid(v.y);
        o2 = fsigmoid(v.z); o3 = fsigmoid(v.w);
    } else if (e == 0) {
        const int p = p0 + lp;
        o0 = (fsigmoid(v.x) + (float)((p    ) % G)) * 8.0f;
        o1 = (fsigmoid(v.y) + (float)((p + 1) % G)) * 8.0f;
        o2 = (fsigmoid(v.z) + (float)((p + 2) % G)) * 8.0f;
        o3 = (fsigmoid(v.w) + (float)((p + 3) % G)) * 8.0f;
    } else if (e == 1) {
        const int p = p0 + lp;
        o0 = (fsigmoid(v.x) + (float)((p    ) / G)) * 8.0f;
        o1 = (fsigmoid(v.y) + (float)((p + 1) / G)) * 8.0f;
        o2 = (fsigmoid(v.z) + (float)((p + 2) / G)) * 8.0f;
        o3 = (fsigmoid(v.w) + (float)((p + 3) / G)) * 8.0f;
    } else if (e == 2) {
        o0 = __expf(v.x) * aw; o1 = __expf(v.y) * aw;
        o2 = __expf(v.z) * aw; o3 = __expf(v.w) * aw;
    } else { // e == 3
        o0 = __expf(v.x) * ah; o1 = __expf(v.y) * ah;
        o2 = __expf(v.z) * ah; o3 = __expf(v.w) * ah;
    }
    float* sp = s + lp * NE + e;     // output layout: word = lp*85 + e
    sp[0 * NE] = o0; sp[1 * NE] = o1; sp[2 * NE] = o2; sp[3 * NE] = o3;
}

__global__ __launch_bounds__(THREADS, 8)
void det_decode_kernel(const float* __restrict__ x, float* __restrict__ out) {
    __shared__ alignas(128) float s[TILE * NE];   // 17,680 B

    // Tile -> (b, a, p0). tiles/anchor = 52, tiles/batch = 156.
    const int t   = blockIdx.x;
    const int b   = t / 156;
    const int rem = t - b * 156;
    const int a   = rem / TILES_PER_PLANE;
    const int pt  = rem - a * TILES_PER_PLANE;
    const int p0  = pt * TILE;

    const float4* __restrict__ src = reinterpret_cast<const float4*>(
        x + (size_t)b * IN_PER_B + (size_t)(a * NE) * GG + p0);

    const float aw = c_aw[a];
    const float ah = c_ah[a];

    const int tid = threadIdx.x;
    const int j0 = tid;
    const int j1 = tid + THREADS;
    const int j2 = tid + 2 * THREADS;
    const int j3 = tid + 3 * THREADS;
    const int j4 = tid + 4 * THREADS;          // valid only for tid < 81
    const bool tail = (j4 < NV);

    // Issue all loads back-to-back (MLP = 5 per thread).
    #define SRCIDX(j) ((j) / QV * GGV + ((j) - (j) / QV * QV))
    const float4 v0 = src[SRCIDX(j0)];
    const float4 v1 = src[SRCIDX(j1)];
    const float4 v2 = src[SRCIDX(j2)];
    const float4 v3 = src[SRCIDX(j3)];
    float4 v4 = make_float4(0.f, 0.f, 0.f, 0.f);
    if (tail) v4 = src[SRCIDX(j4)];
    #undef SRCIDX

    transform_store(s, v0, j0, p0, aw, ah);
    transform_store(s, v1, j1, p0, aw, ah);
    transform_store(s, v2, j2, p0, aw, ah);
    transform_store(s, v3, j3, p0, aw, ah);
    if (tail) transform_store(s, v4, j4, p0, aw, ah);

    __syncthreads();

    // Phase 2: tile's output is one contiguous span of TILE*NE = 4420 floats.
    float4* __restrict__ dst =
        reinterpret_cast<float4*>(out + (size_t)t * (TILE * NE));
    const float4* __restrict__ ss = reinterpret_cast<const float4*>(s);
    #pragma unroll 5
    for (int j = tid; j < NV; j += THREADS) {
        __stcs(dst + j, ss[j]);
    }
}

extern "C" void kernel_launch(void* const* d_in, const int* in_sizes, int n_in,
                              void* d_out, int out_size) {
    const float* x = (const float*)d_in[0];
    float* out = (float*)d_out;
    const int blocks = out_size / (TILE * NE);   // 9984
    det_decode_kernel<<<blocks, THREADS>>>(x, out);
}

// round 16
// speedup vs baseline: 1.6571x; 1.0084x over previous
#include <cuda_runtime.h>
#include <cstdint>

// YOLO detection decode: x (64, 255, 52, 52) f32 -> out (64, 8112, 85) f32
// FINAL (v9-family, converged over 14 rounds; best bench 56.1us, DRAM 72%).
//   - 9984 small independent blocks (256 thr, one 52-row tile in one
//     (batch,anchor) plane) -> natural phase desync across 8 CTAs/SM
//   - batched 4+1 LDG.128 per thread issued back-to-back (MLP=5)
//   - default-cached loads (boundary 32B sectors shared between tiles;
//     L2 dedups them -> measured DRAM traffic 297MB < 353MB nominal)
//   - tanh.approx sigmoid (1 MUFU), exp only for w/h channels
//   - scalar-STS transpose into output-layout smem (~2-way conflicts;
//     swizzles cost more ALU than they save)
//   - contiguous float4 streaming STG of the tile's 17680B output span
//   Rejected by measurement: smem swizzles (R4/5), TMA bulk store (R6/7),
//   double-buffer pipeline (R10), persistent grid (R11), 2-tile chunks (R12),
//   2x scale-up (R13).

#define G 52
#define GG 2704              // G*G
#define GGV 676              // GG/4 (channel stride in float4)
#define IN_PER_B 689520      // 255*GG
#define NE 85
#define TILE 52
#define QV 13                // TILE/4
#define NV (NE * QV)         // 1105 float4 per tile
#define TILES_PER_PLANE 52
#define THREADS 256

__constant__ float c_aw[3] = {10.0f, 16.0f, 33.0f};
__constant__ float c_ah[3] = {13.0f, 30.0f, 23.0f};

__device__ __forceinline__ float fsigmoid(float v) {
    // sigmoid(v) = 0.5 + 0.5*tanh(0.5*v); MUFU.TANH, abs err ~2^-12
    float t;
    asm("tanh.approx.f32 %0, %1;" : "=f"(t) : "f"(0.5f * v));
    return fmaf(0.5f, t, 0.5f);
}

__device__ __forceinline__ void transform_store(
    float* __restrict__ s, float4 v, int j, int p0, float aw, float ah) {
    const int e = j / QV;
    const int q = j - e * QV;
    const int lp = q * 4;

    float o0, o1, o2, o3;
    if (e >= 4) {
        o0 = fsigmoid(v.x); o1 = fsigmoid(v.y);
        o2 = fsigmoid(v.z); o3 = fsigmoid(v.w);
    } else if (e == 0) {
        const int p = p0 + lp;
        o0 = (fsigmoid(v.x) + (float)((p    ) % G)) * 8.0f;
        o1 = (fsigmoid(v.y) + (float)((p + 1) % G)) * 8.0f;
        o2 = (fsigmoid(v.z) + (float)((p + 2) % G)) * 8.0f;
        o3 = (fsigmoid(v.w) + (float)((p + 3) % G)) * 8.0f;
    } else if (e == 1) {
        const int p = p0 + lp;
        o0 = (fsigmoid(v.x) + (float)((p    ) / G)) * 8.0f;
        o1 = (fsigmoid(v.y) + (float)((p + 1) / G)) * 8.0f;
        o2 = (fsigmoid(v.z) + (float)((p + 2) / G)) * 8.0f;
        o3 = (fsigmoid(v.w) + (float)((p + 3) / G)) * 8.0f;
    } else if (e == 2) {
        o0 = __expf(v.x) * aw; o1 = __expf(v.y) * aw;
        o2 = __expf(v.z) * aw; o3 = __expf(v.w) * aw;
    } else { // e == 3
        o0 = __expf(v.x) * ah; o1 = __expf(v.y) * ah;
        o2 = __expf(v.z) * ah; o3 = __expf(v.w) * ah;
    }
    float* sp = s + lp * NE + e;     // output layout: word = lp*85 + e
    sp[0 * NE] = o0; sp[1 * NE] = o1; sp[2 * NE] = o2; sp[3 * NE] = o3;
}

__global__ __launch_bounds__(THREADS, 8)
void det_decode_kernel(const float* __restrict__ x, float* __restrict__ out) {
    __shared__ alignas(128) float s[TILE * NE];   // 17,680 B

    // Tile -> (b, a, p0). tiles/anchor = 52, tiles/batch = 156.
    const int t   = blockIdx.x;
    const int b   = t / 156;
    const int rem = t - b * 156;
    const int a   = rem / TILES_PER_PLANE;
    const int pt  = rem - a * TILES_PER_PLANE;
    const int p0  = pt * TILE;

    const float4* __restrict__ src = reinterpret_cast<const float4*>(
        x + (size_t)b * IN_PER_B + (size_t)(a * NE) * GG + p0);

    const float aw = c_aw[a];
    const float ah = c_ah[a];

    const int tid = threadIdx.x;
    const int j0 = tid;
    const int j1 = tid + THREADS;
    const int j2 = tid + 2 * THREADS;
    const int j3 = tid + 3 * THREADS;
    const int j4 = tid + 4 * THREADS;          // valid only for tid < 81
    const bool tail = (j4 < NV);

    // Precompute all source indices, then issue loads back-to-back (MLP = 5).
    #define SRCIDX(j) ((j) / QV * GGV + ((j) - (j) / QV * QV))
    const int i0 = SRCIDX(j0);
    const int i1 = SRCIDX(j1);
    const int i2 = SRCIDX(j2);
    const int i3 = SRCIDX(j3);
    const int i4 = tail ? SRCIDX(j4) : 0;
    #undef SRCIDX

    const float4 v0 = src[i0];
    const float4 v1 = src[i1];
    const float4 v2 = src[i2];
    const float4 v3 = src[i3];
    float4 v4 = make_float4(0.f, 0.f, 0.f, 0.f);
    if (tail) v4 = src[i4];

    transform_store(s, v0, j0, p0, aw, ah);
    transform_store(s, v1, j1, p0, aw, ah);
    transform_store(s, v2, j2, p0, aw, ah);
    transform_store(s, v3, j3, p0, aw, ah);
    if (tail) transform_store(s, v4, j4, p0, aw, ah);

    __syncthreads();

    // Phase 2: tile's output is one contiguous span of TILE*NE = 4420 floats.
    float4* __restrict__ dst =
        reinterpret_cast<float4*>(out + (size_t)t * (TILE * NE));
    const float4* __restrict__ ss = reinterpret_cast<const float4*>(s);
    __stcs(dst + j0, ss[j0]);
    __stcs(dst + j1, ss[j1]);
    __stcs(dst + j2, ss[j2]);
    __stcs(dst + j3, ss[j3]);
    if (tail) __stcs(dst + j4, ss[j4]);
}

extern "C" void kernel_launch(void* const* d_in, const int* in_sizes, int n_in,
                              void* d_out, int out_size) {
    const float* x = (const float*)d_in[0];
    float* out = (float*)d_out;
    const int blocks = out_size / (TILE * NE);   // 9984
    det_decode_kernel<<<blocks, THREADS>>>(x, out);
}